// round 2
// baseline (speedup 1.0000x reference)
#include <cuda_runtime.h>
#include <math.h>

#define NN 100000
#define FD 128
#define OUTF 64
#define EMAX 1600000
#define SCHUNK 512
#define NBLKMAX ((NN + SCHUNK - 1) / SCHUNK)

// Scratch (static __device__ to satisfy no-alloc rule)
__device__ float g_bufA[NN * FD];   // hs (layer1 scaled) then ts (layer2 scaled)
__device__ float g_bufB[NN * FD];   // H (aggregated layer1 output)
__device__ int   g_cnt[NN];
__device__ int   g_partial[NN];
__device__ int   g_rowptr[NN + 1];
__device__ int   g_rowcur[NN];
__device__ float g_dinv[NN];
__device__ int   g_esrc[EMAX];
__device__ int   g_bsum[NBLKMAX];
__device__ int   g_boff[NBLKMAX];

// ---- packed f32x2 helpers (sm_100+) ----
__device__ __forceinline__ unsigned long long pk2(float v) {
    unsigned long long r;
    asm("mov.b64 %0,{%1,%1};" : "=l"(r) : "f"(v));
    return r;
}
__device__ __forceinline__ float2 upk2(unsigned long long v) {
    float2 r;
    asm("mov.b64 {%0,%1},%2;" : "=f"(r.x), "=f"(r.y) : "l"(v));
    return r;
}
__device__ __forceinline__ unsigned long long ffma2(unsigned long long a,
                                                    unsigned long long b,
                                                    unsigned long long c) {
    unsigned long long d;
    asm("fma.rn.f32x2 %0,%1,%2,%3;" : "=l"(d) : "l"(a), "l"(b), "l"(c));
    return d;
}

// ---------- graph prep ----------
__global__ void k_zero(int n) {
    int i = blockIdx.x * blockDim.x + threadIdx.x;
    if (i < n) g_cnt[i] = 0;
}

__global__ void k_count(const int* __restrict__ dst, int E) {
    int e = blockIdx.x * blockDim.x + threadIdx.x;
    if (e < E) atomicAdd(&g_cnt[dst[e]], 1);
}

__global__ void k_scan1(int n) {
    __shared__ int sm[SCHUNK];
    int i = blockIdx.x * SCHUNK + threadIdx.x;
    int v = (i < n) ? g_cnt[i] : 0;
    sm[threadIdx.x] = v;
    __syncthreads();
    for (int off = 1; off < SCHUNK; off <<= 1) {
        int t = (threadIdx.x >= (unsigned)off) ? sm[threadIdx.x - off] : 0;
        __syncthreads();
        sm[threadIdx.x] += t;
        __syncthreads();
    }
    if (i < n) g_partial[i] = sm[threadIdx.x];
    if (threadIdx.x == SCHUNK - 1) g_bsum[blockIdx.x] = sm[threadIdx.x];
}

__global__ void k_scan2(int nblk) {
    __shared__ int sm[SCHUNK];
    int t = threadIdx.x;
    int mine = (t < nblk) ? g_bsum[t] : 0;
    sm[t] = mine;
    __syncthreads();
    for (int off = 1; off < SCHUNK; off <<= 1) {
        int v = (t >= off) ? sm[t - off] : 0;
        __syncthreads();
        sm[t] += v;
        __syncthreads();
    }
    if (t < nblk) g_boff[t] = sm[t] - mine;   // exclusive
}

__global__ void k_rows(int n, int E) {
    int i = blockIdx.x * blockDim.x + threadIdx.x;
    if (i < n) {
        int c = g_cnt[i];
        int rp = g_partial[i] + g_boff[i / SCHUNK] - c;
        g_rowptr[i] = rp;
        g_rowcur[i] = rp;
        g_dinv[i] = rsqrtf((float)(c + 1));   // self-loop -> deg >= 1
        if (i == 0) g_rowptr[n] = E;
    }
}

__global__ void k_scatter(const int* __restrict__ src, const int* __restrict__ dst, int E) {
    int e = blockIdx.x * blockDim.x + threadIdx.x;
    if (e < E) {
        int d = dst[e];
        int pos = atomicAdd(&g_rowcur[d], 1);
        g_esrc[pos] = src[e];
    }
}

// ---------- GEMM: out[i] = dinv[i] * (A[i] @ W), W 128x128 in smem ----------
// concat==1: W = [Wa(128x64) | Wb(128x64)]
__global__ void k_gemm(const float* __restrict__ A,
                       const float* __restrict__ Wa,
                       const float* __restrict__ Wb,
                       int concat,
                       float* __restrict__ out, int n) {
    extern __shared__ float smem[];
    float* Wsm = smem;                 // 128*128 floats
    float* Xs  = smem + FD * FD;       // 8 warps * 4 rows * 128 floats

    for (int idx = threadIdx.x; idx < FD * FD; idx += blockDim.x) {
        float w;
        if (concat) {
            int k = idx >> 7, j = idx & 127;
            w = (j < OUTF) ? Wa[(k << 6) + j] : Wb[(k << 6) + (j - OUTF)];
        } else {
            w = Wa[idx];
        }
        Wsm[idx] = w;
    }
    __syncthreads();

    int warp = threadIdx.x >> 5, lane = threadIdx.x & 31;
    int row0 = blockIdx.x * 32 + warp * 4;
    float* xs = Xs + warp * (4 * FD);

#pragma unroll
    for (int r = 0; r < 4; r++) {
        int row = row0 + r;
        float4 v = make_float4(0.f, 0.f, 0.f, 0.f);
        if (row < n) v = ((const float4*)A)[row * (FD / 4) + lane];
        ((float4*)(xs + r * FD))[lane] = v;
    }
    __syncwarp();

    unsigned long long a00 = 0, a01 = 0, a10 = 0, a11 = 0;
    unsigned long long a20 = 0, a21 = 0, a30 = 0, a31 = 0;
    const ulonglong2* Wp = (const ulonglong2*)Wsm;

#pragma unroll 4
    for (int k = 0; k < FD; k++) {
        ulonglong2 w = Wp[k * (FD / 4) + lane];
        unsigned long long p0 = pk2(xs[k]);
        unsigned long long p1 = pk2(xs[FD + k]);
        unsigned long long p2 = pk2(xs[2 * FD + k]);
        unsigned long long p3 = pk2(xs[3 * FD + k]);
        a00 = ffma2(p0, w.x, a00);  a01 = ffma2(p0, w.y, a01);
        a10 = ffma2(p1, w.x, a10);  a11 = ffma2(p1, w.y, a11);
        a20 = ffma2(p2, w.x, a20);  a21 = ffma2(p2, w.y, a21);
        a30 = ffma2(p3, w.x, a30);  a31 = ffma2(p3, w.y, a31);
    }

#pragma unroll
    for (int r = 0; r < 4; r++) {
        int row = row0 + r;
        if (row >= n) break;
        unsigned long long lo64 = (r == 0) ? a00 : (r == 1) ? a10 : (r == 2) ? a20 : a30;
        unsigned long long hi64 = (r == 0) ? a01 : (r == 1) ? a11 : (r == 2) ? a21 : a31;
        float sc = g_dinv[row];
        float2 lo = upk2(lo64), hi = upk2(hi64);
        float4 o = make_float4(lo.x * sc, lo.y * sc, hi.x * sc, hi.y * sc);
        ((float4*)out)[row * (FD / 4) + lane] = o;
    }
}

// ---------- aggregation 1: out[d] = dinv[d]*(sum_in hs[src] + hs[d]) + b ----------
__global__ void k_agg1(const float* __restrict__ S,
                       const float* __restrict__ bias,
                       float* __restrict__ out, int n) {
    int gw = (blockIdx.x * blockDim.x + threadIdx.x) >> 5;
    if (gw >= n) return;
    int lane = threadIdx.x & 31;
    const float4* Sv = (const float4*)S;
    int beg = g_rowptr[gw], end = g_rowptr[gw + 1];
    float4 a = Sv[gw * 32 + lane];   // self-loop term
#pragma unroll 4
    for (int e = beg; e < end; e++) {
        int s = g_esrc[e];
        float4 v = Sv[s * 32 + lane];
        a.x += v.x; a.y += v.y; a.z += v.z; a.w += v.w;
    }
    float sc = g_dinv[gw];
    float4 b = ((const float4*)bias)[lane];
    float4 o = make_float4(a.x * sc + b.x, a.y * sc + b.y,
                           a.z * sc + b.z, a.w * sc + b.w);
    ((float4*)out)[gw * 32 + lane] = o;
}

// ---------- aggregation 2 + reparametrize ----------
// S row layout: [mu(64) | logstd(64)] (pre-scaled by dinv[src]).
// lane l handles cols 4l..4l+3; lane l (<16) pairs with lane l+16 via shfl_xor(16).
__global__ void k_agg2(const float* __restrict__ S,
                       const float* __restrict__ bmu,
                       const float* __restrict__ bls,
                       const float* __restrict__ initd,
                       float* __restrict__ out, int n) {
    int gw = (blockIdx.x * blockDim.x + threadIdx.x) >> 5;
    if (gw >= n) return;
    int lane = threadIdx.x & 31;
    const float4* Sv = (const float4*)S;
    int beg = g_rowptr[gw], end = g_rowptr[gw + 1];
    float4 a = Sv[gw * 32 + lane];
#pragma unroll 4
    for (int e = beg; e < end; e++) {
        int s = g_esrc[e];
        float4 v = Sv[s * 32 + lane];
        a.x += v.x; a.y += v.y; a.z += v.z; a.w += v.w;
    }
    float sc = g_dinv[gw];
    a.x *= sc; a.y *= sc; a.z *= sc; a.w *= sc;

    float ox = __shfl_xor_sync(0xffffffffu, a.x, 16);
    float oy = __shfl_xor_sync(0xffffffffu, a.y, 16);
    float oz = __shfl_xor_sync(0xffffffffu, a.z, 16);
    float ow = __shfl_xor_sync(0xffffffffu, a.w, 16);

    if (lane < 16) {
        float4 bm = ((const float4*)bmu)[lane];
        float4 bl = ((const float4*)bls)[lane];
        float4 iv = ((const float4*)initd)[gw * 16 + lane];
        float4 r;
        r.x = (a.x + bm.x) + iv.x * expf(ox + bl.x);
        r.y = (a.y + bm.y) + iv.y * expf(oy + bl.y);
        r.z = (a.z + bm.z) + iv.z * expf(oz + bl.z);
        r.w = (a.w + bm.w) + iv.w * expf(ow + bl.w);
        ((float4*)out)[gw * 16 + lane] = r;
    }
}

#define SMEM_GEMM ((FD * FD + 8 * 4 * FD) * (int)sizeof(float))

extern "C" void kernel_launch(void* const* d_in, const int* in_sizes, int n_in,
                              void* d_out, int out_size) {
    const float* x     = (const float*)d_in[0];
    const int*   ei    = (const int*)d_in[1];
    const float* initd = (const float*)d_in[2];
    const float* W1    = (const float*)d_in[3];
    const float* b1    = (const float*)d_in[4];
    const float* Wmu   = (const float*)d_in[5];
    const float* bmu   = (const float*)d_in[6];
    const float* Wls   = (const float*)d_in[7];
    const float* bls   = (const float*)d_in[8];
    float* out = (float*)d_out;

    int n = in_sizes[0] / FD;
    int E = in_sizes[1] / 2;
    const int* src = ei;
    const int* dst = ei + E;

    void *pA = nullptr, *pB = nullptr;
    cudaGetSymbolAddress(&pA, g_bufA);
    cudaGetSymbolAddress(&pB, g_bufB);
    float* bufA = (float*)pA;
    float* bufB = (float*)pB;

    cudaFuncSetAttribute(k_gemm, cudaFuncAttributeMaxDynamicSharedMemorySize, SMEM_GEMM);

    // graph prep
    k_zero<<<(n + 255) / 256, 256>>>(n);
    k_count<<<(E + 255) / 256, 256>>>(dst, E);
    int nblk = (n + SCHUNK - 1) / SCHUNK;
    k_scan1<<<nblk, SCHUNK>>>(n);
    k_scan2<<<1, SCHUNK>>>(nblk);
    k_rows<<<(n + 255) / 256, 256>>>(n, E);
    k_scatter<<<(E + 255) / 256, 256>>>(src, dst, E);

    // layer 1: hs = dinv .* (x @ W1);  H = dinv .* (scatter-sum hs) + b1
    k_gemm<<<(n + 31) / 32, 256, SMEM_GEMM>>>(x, W1, nullptr, 0, bufA, n);
    k_agg1<<<(n * 32 + 255) / 256, 256>>>(bufA, b1, bufB, n);

    // layer 2+3 fused: ts = dinv .* (H @ [Wmu|Wls]); aggregate + reparametrize
    k_gemm<<<(n + 31) / 32, 256, SMEM_GEMM>>>(bufB, Wmu, Wls, 1, bufA, n);
    k_agg2<<<(n * 32 + 255) / 256, 256>>>(bufA, bmu, bls, initd, out, n);
}